// round 15
// baseline (speedup 1.0000x reference)
#include <cuda_runtime.h>
#include <cuda_fp16.h>
#include <cstdint>
#include <math.h>

#define BB 2
#define TT 2048
#define DD 1024
#define HH 16
#define FF 4096
#define NROWS (BB*TT)
#define NBH (BB*HH)

// ================= scratch =================
__device__ __align__(256) __half  g_h16 [NROWS*DD];
__device__ __align__(256) __half  g_qkv [3*(size_t)NROWS*DD];
__device__ __align__(256) __half  g_att [NROWS*DD];
__device__ __align__(256) float   g_x2  [NROWS*DD];
__device__ __align__(256) __half  g_h216[NROWS*DD];
__device__ __align__(256) __half  g_ff  [(size_t)NROWS*FF];
__device__ __align__(256) __half  g_wqkvT[3*(size_t)DD*DD];
__device__ __align__(256) __half  g_wpT [(size_t)DD*DD];
__device__ __align__(256) __half  g_w1T [(size_t)FF*DD];
__device__ __align__(256) __half  g_w2T [(size_t)DD*FF];
__device__ __align__(256) uint32_t g_mb [BB*TT*(TT/32)];
__device__ __align__(256) int      g_mf [BB*32];
__device__ __align__(256) float2  g_rt  [TT*32];

// scale folded into Q: 1/sqrt(64) * log2(e)  (softmax done in exp2 domain)
#define QSCALE_LOG2E 0.18033688011112042f

// ================= helpers =================
__device__ __forceinline__ uint32_t smem_u32(const void* p) {
    uint32_t a;
    asm("{ .reg .u64 t; cvta.to.shared.u64 t, %1; cvt.u32.u64 %0, t; }" : "=r"(a) : "l"(p));
    return a;
}
#define CPA(dst, src) \
    asm volatile("cp.async.cg.shared.global [%0], [%1], 16;" :: "r"(dst), "l"(src) : "memory")
#define CPCOMMIT asm volatile("cp.async.commit_group;" ::: "memory")
#define CPWAIT(n) asm volatile("cp.async.wait_group %0;" :: "n"(n) : "memory")

__device__ __forceinline__ void ldsm4(uint32_t& r0, uint32_t& r1, uint32_t& r2, uint32_t& r3, uint32_t a) {
    asm volatile("ldmatrix.sync.aligned.m8n8.x4.shared.b16 {%0,%1,%2,%3}, [%4];"
        : "=r"(r0), "=r"(r1), "=r"(r2), "=r"(r3) : "r"(a));
}
__device__ __forceinline__ void ldsm4t(uint32_t& r0, uint32_t& r1, uint32_t& r2, uint32_t& r3, uint32_t a) {
    asm volatile("ldmatrix.sync.aligned.m8n8.x4.trans.shared.b16 {%0,%1,%2,%3}, [%4];"
        : "=r"(r0), "=r"(r1), "=r"(r2), "=r"(r3) : "r"(a));
}
__device__ __forceinline__ void mma_f16(float* c, const uint32_t* a, uint32_t b0, uint32_t b1) {
    asm volatile("mma.sync.aligned.m16n8k16.row.col.f32.f16.f16.f32 "
        "{%0,%1,%2,%3}, {%4,%5,%6,%7}, {%8,%9}, {%0,%1,%2,%3};"
        : "+f"(c[0]), "+f"(c[1]), "+f"(c[2]), "+f"(c[3])
        : "r"(a[0]), "r"(a[1]), "r"(a[2]), "r"(a[3]), "r"(b0), "r"(b1));
}
__device__ __forceinline__ uint32_t packh2(float a, float b) {
    __half2 h = __floats2half2_rn(a, b);
    return *(uint32_t*)&h;
}

// ================= uber preprocessing kernel =================
// grid ranges: [0,12288) wtall  [12288,13312) packmask  [13312,13568) ropetab
//              [13568,17664) LN1
__global__ void __launch_bounds__(256) prep_kernel(
        const float* __restrict__ wq, const float* __restrict__ wk,
        const float* __restrict__ wv, const float* __restrict__ wp,
        const float* __restrict__ w1, const float* __restrict__ w2,
        __half* __restrict__ oqkv, __half* __restrict__ op,
        __half* __restrict__ o1, __half* __restrict__ o2,
        const int* __restrict__ mask, uint32_t* __restrict__ mb,
        float2* __restrict__ rt,
        const float* __restrict__ x, const float* __restrict__ g1,
        const float* __restrict__ b1v, __half* __restrict__ h16out) {
    __shared__ float shm[32*33];
    int bid = blockIdx.x;
    int tid = threadIdx.x;

    if (bid < 12288) {
        const float* W; __half* out; int K, N, tile;
        if (bid < 3072)      { int w = bid >> 10; W = (w==0)?wq:((w==1)?wk:wv);
                               out = oqkv + (size_t)w*DD*DD; K = DD; N = DD; tile = bid & 1023; }
        else if (bid < 4096) { W = wp; out = op; K = DD; N = DD; tile = bid - 3072; }
        else if (bid < 8192) { W = w1; out = o1; K = DD; N = FF; tile = bid - 4096; }
        else                 { W = w2; out = o2; K = FF; N = DD; tile = bid - 8192; }
        int ntx = N >> 5;
        int n0 = (tile % ntx) << 5, k0 = (tile / ntx) << 5;
        int tx = tid & 31, ty = tid >> 5;
#pragma unroll
        for (int r = 0; r < 4; r++)
            shm[(ty + 8*r)*33 + tx] = W[(size_t)(k0 + ty + 8*r) * N + n0 + tx];
        __syncthreads();
#pragma unroll
        for (int r = 0; r < 4; r++)
            out[(size_t)(n0 + ty + 8*r) * K + k0 + tx] = __float2half_rn(shm[tx*33 + ty + 8*r]);
    } else if (bid < 13312) {
        int wi = (bid - 12288) * 256 + tid;
        const int4* p = (const int4*)(mask + (size_t)wi * 32);
        uint32_t w = 0;
#pragma unroll
        for (int j = 0; j < 8; j++) {
            int4 v = p[j];
            w |= (uint32_t)(v.x != 0) << (j*4 + 0);
            w |= (uint32_t)(v.y != 0) << (j*4 + 1);
            w |= (uint32_t)(v.z != 0) << (j*4 + 2);
            w |= (uint32_t)(v.w != 0) << (j*4 + 3);
        }
        mb[wi] = w;
    } else if (bid < 13568) {
        int idx = (bid - 13312) * 256 + tid;
        int t = idx >> 5, pi = idx & 31;
        float theta = expf(-((2.0f * pi) / 64.0f) * logf(10000.0f));
        float ang = (float)t * theta;
        rt[idx] = make_float2(cosf(ang), sinf(ang));
    } else {
        int row = bid - 13568;
        const float4 f = ((const float4*)(x + (size_t)row * DD))[tid];
        int wid = tid >> 5, lane = tid & 31;

        float s = f.x + f.y + f.z + f.w;
#pragma unroll
        for (int o = 16; o; o >>= 1) s += __shfl_xor_sync(~0u, s, o);
        if (lane == 0) shm[wid] = s;
        __syncthreads();
        s = shm[lane & 7];
#pragma unroll
        for (int o = 4; o; o >>= 1) s += __shfl_xor_sync(~0u, s, o);
        float mean = s * (1.0f / DD);

        float dx = f.x - mean, dy = f.y - mean, dz = f.z - mean, dw = f.w - mean;
        float v = dx*dx + dy*dy + dz*dz + dw*dw;
#pragma unroll
        for (int o = 16; o; o >>= 1) v += __shfl_xor_sync(~0u, v, o);
        __syncthreads();
        if (lane == 0) shm[wid] = v;
        __syncthreads();
        v = shm[lane & 7];
#pragma unroll
        for (int o = 4; o; o >>= 1) v += __shfl_xor_sync(~0u, v, o);
        float inv = rsqrtf(v * (1.0f / DD) + 1e-5f);

        const float4 g4 = ((const float4*)g1)[tid];
        const float4 b4 = ((const float4*)b1v)[tid];
        uint2 st;
        st.x = packh2(dx*inv*g4.x + b4.x, dy*inv*g4.y + b4.y);
        st.y = packh2(dz*inv*g4.z + b4.z, dw*inv*g4.w + b4.w);
        *(uint2*)(h16out + (size_t)row * DD + tid*4) = st;
    }
}

// ================= LayerNorm -> fp16 (standalone for LN2) =================
__global__ void ln16_kernel(const float* __restrict__ x, const float* __restrict__ g,
                            const float* __restrict__ b, __half* __restrict__ out) {
    int row = blockIdx.x;
    int tid = threadIdx.x;
    const float4 f = ((const float4*)(x + (size_t)row * DD))[tid];
    __shared__ float sw[8];
    int wid = tid >> 5, lane = tid & 31;

    float s = f.x + f.y + f.z + f.w;
#pragma unroll
    for (int o = 16; o; o >>= 1) s += __shfl_xor_sync(~0u, s, o);
    if (lane == 0) sw[wid] = s;
    __syncthreads();
    s = sw[lane & 7];
#pragma unroll
    for (int o = 4; o; o >>= 1) s += __shfl_xor_sync(~0u, s, o);
    float mean = s * (1.0f / DD);

    float dx = f.x - mean, dy = f.y - mean, dz = f.z - mean, dw = f.w - mean;
    float v = dx*dx + dy*dy + dz*dz + dw*dw;
#pragma unroll
    for (int o = 16; o; o >>= 1) v += __shfl_xor_sync(~0u, v, o);
    __syncthreads();
    if (lane == 0) sw[wid] = v;
    __syncthreads();
    v = sw[lane & 7];
#pragma unroll
    for (int o = 4; o; o >>= 1) v += __shfl_xor_sync(~0u, v, o);
    float inv = rsqrtf(v * (1.0f / DD) + 1e-5f);

    const float4 g4 = ((const float4*)g)[tid];
    const float4 b4 = ((const float4*)b)[tid];
    uint2 st;
    st.x = packh2(dx*inv*g4.x + b4.x, dy*inv*g4.y + b4.y);
    st.y = packh2(dz*inv*g4.z + b4.z, dw*inv*g4.w + b4.w);
    *(uint2*)(out + (size_t)row * DD + tid*4) = st;
}

// ================= per-(b, key-block) all/any flags (reads packed mb) ==========
__global__ void maskflags_kernel(const uint32_t* __restrict__ mb, int* __restrict__ mf) {
    int bs = blockIdx.x;
    int b = bs >> 5, sblk = bs & 31;
    uint32_t av = 0xFFFFFFFFu, ov = 0u;
    for (int t = threadIdx.x; t < TT; t += 256) {
        const uint32_t* p = mb + ((size_t)(b*TT) + t)*(TT/32) + sblk*2;
        uint32_t w0 = p[0], w1 = p[1];
        av &= (w0 & w1); ov |= (w0 | w1);
    }
    __shared__ uint32_t sa[8], so[8];
#pragma unroll
    for (int o = 16; o; o >>= 1) {
        av &= __shfl_xor_sync(~0u, av, o);
        ov |= __shfl_xor_sync(~0u, ov, o);
    }
    int w = threadIdx.x >> 5;
    if ((threadIdx.x & 31) == 0) { sa[w] = av; so[w] = ov; }
    __syncthreads();
    if (threadIdx.x == 0) {
        av = 0xFFFFFFFFu; ov = 0u;
#pragma unroll
        for (int i = 0; i < 8; i++) { av &= sa[i]; ov |= so[i]; }
        mf[bs] = ((av == 0xFFFFFFFFu) ? 2 : 0) | (ov ? 1 : 0);
    }
}

// ================= mma.sync fp16 GEMM (128x128, 3-stage, 2 CTA/SM) — proven ====
// EPI bits: 1=ROPE(z<2), 2=BIAS, 4=RELU, 8=RES, 16=F16OUT, 32=QSCALE(z==0)
template<int EPI>
__global__ void __launch_bounds__(256, 2) mm16(
        const __half* __restrict__ A, const __half* __restrict__ B0,
        const float* __restrict__ bias, const float* __restrict__ res,
        float* __restrict__ outF, __half* __restrict__ outH0,
        int N, int K, long zsB, long zsC, const float2* __restrict__ rt) {
    extern __shared__ char smem_raw[];
    const uint32_t sbr = smem_u32(smem_raw);
    const uint32_t sb = (sbr + 1023) & ~1023u;

    const int tid = threadIdx.x, wid = tid >> 5, lane = tid & 31;
    const int wm = wid >> 1, wn = wid & 1;
    const int m0 = blockIdx.y << 7, n0 = blockIdx.x << 7;
    const int NC = K >> 6;

    const __half* Bw = B0 + (size_t)blockIdx.z * zsB;
    __half* outH = outH0 + (size_t)blockIdx.z * zsC;

    const __half* Ag = A  + (size_t)m0 * K;
    const __half* Bg = Bw + (size_t)n0 * K;

    const int rq_r = tid >> 3, rq_q = tid & 7;
    const __half* agp = Ag + (size_t)rq_r * K + (rq_q << 3);
    const __half* bgp = Bg + (size_t)rq_r * K + (rq_q << 3);
    uint32_t so = (uint32_t)((rq_r << 7) + (rq_q << 4));
    so ^= (so >> 3) & 0x70;
    const size_t rowstep = (size_t)32 * K;

    auto issue_load = [&](int c, int stg) {
        uint32_t sA = sb + stg * 32768;
#pragma unroll
        for (int v = 0; v < 4; v++) {
            CPA(sA + so + v*4096,         agp + (size_t)c*64 + v*rowstep);
            CPA(sA + 16384 + so + v*4096, bgp + (size_t)c*64 + v*rowstep);
        }
    };

    float acc[2][8][4];
#pragma unroll
    for (int mi = 0; mi < 2; mi++)
#pragma unroll
        for (int ni = 0; ni < 8; ni++)
#pragma unroll
            for (int v = 0; v < 4; v++) acc[mi][ni][v] = 0.f;

#pragma unroll
    for (int s = 0; s < 3; s++) { issue_load(s, s); CPCOMMIT; }

    for (int c = 0; c < NC; c++) {
        CPWAIT(2);
        __syncthreads();
        int stg = c % 3;
        uint32_t sA = sb + stg * 32768;
        uint32_t sB = sA + 16384;
#pragma unroll
        for (int kk = 0; kk < 4; kk++) {
            uint32_t a[2][4], b0[8], b1[8];
            const int kb = kk*32 + ((lane >> 4) << 4);
#pragma unroll
            for (int mi = 0; mi < 2; mi++) {
                int row = wm*32 + mi*16 + (lane & 15);
                uint32_t o = (uint32_t)(row*128 + kb); o ^= (o >> 3) & 0x70;
                ldsm4(a[mi][0], a[mi][1], a[mi][2], a[mi][3], sA + o);
            }
#pragma unroll
            for (int j = 0; j < 4; j++) {
                int row = wn*64 + j*16 + (lane & 15);
                uint32_t o = (uint32_t)(row*128 + kb); o ^= (o >> 3) & 0x70;
                ldsm4(b0[2*j], b0[2*j+1], b1[2*j], b1[2*j+1], sB + o);
            }
#pragma unroll
            for (int mi = 0; mi < 2; mi++)
#pragma unroll
                for (int ni = 0; ni < 8; ni++)
                    mma_f16(acc[mi][ni], a[mi], b0[ni], b1[ni]);
        }
        __syncthreads();
        if (c + 3 < NC) issue_load(c + 3, stg);
        CPCOMMIT;
    }
    CPWAIT(0);

    // epilogue
    const int g = lane >> 2, tq = lane & 3;
    const bool doRope = (EPI & 1) && (blockIdx.z < 2);
    const bool doQs   = (EPI & 32) && (blockIdx.z == 0);
#pragma unroll
    for (int mi = 0; mi < 2; mi++) {
#pragma unroll
        for (int ni = 0; ni < 8; ni++) {
            const int colb = n0 + wn*64 + ni*8 + 2*tq;
            float2 bv = make_float2(0.f, 0.f);
            if (EPI & 2) bv = *(const float2*)(bias + colb);
#pragma unroll
            for (int rh = 0; rh < 2; rh++) {
                int row = m0 + wm*32 + mi*16 + g + rh*8;
                float v0 = acc[mi][ni][rh*2], v1 = acc[mi][ni][rh*2+1];
                if (EPI & 2) { v0 += bv.x; v1 += bv.y; }
                if (EPI & 4) { v0 = fmaxf(v0, 0.f); v1 = fmaxf(v1, 0.f); }
                if (doRope) {
                    int t = row & (TT-1);
                    int pi = (colb & 63) >> 1;
                    float2 cs = rt[t*32 + pi];
                    float nv0 = v0*cs.x - v1*cs.y;
                    float nv1 = v0*cs.y + v1*cs.x;
                    v0 = nv0; v1 = nv1;
                }
                if (doQs) { v0 *= QSCALE_LOG2E; v1 *= QSCALE_LOG2E; }
                if (EPI & 8) {
                    float2 rv = *(const float2*)(res + (size_t)row*N + colb);
                    v0 += rv.x; v1 += rv.y;
                }
                if (EPI & 16) {
                    uint32_t hv = packh2(v0, v1);
                    *(uint32_t*)(outH + (size_t)row*N + colb) = hv;
                } else {
                    *(float2*)(outF + (size_t)row*N + colb) = make_float2(v0, v1);
                }
            }
        }
    }
}

// ================= flash attention: exp2 fp16x2, 3-stage KV pipeline ============
__global__ void __launch_bounds__(256, 2) flash_kernel(
        const __half* __restrict__ qg, const __half* __restrict__ kg, const __half* __restrict__ vg,
        const uint32_t* __restrict__ mb, const int* __restrict__ mf,
        __half* __restrict__ attH) {
    extern __shared__ char smem_raw[];
    const uint32_t sbr = smem_u32(smem_raw);
    const uint32_t sb = (sbr + 1023) & ~1023u;
    char* base = smem_raw + (int)(sb - sbr);

    // layout: Q 16K | K 3x8K | V 3x8K | P 16K   (80K total)
    const uint32_t sQ = sb, sK = sb + 16384, sV = sb + 40960, sP = sb + 65536;

    int bh = blockIdx.y, b = bh >> 4, h = bh & 15;
    int t0 = blockIdx.x << 7;
    int tid = threadIdx.x, wid = tid >> 5, lane = tid & 31;
    int g = lane >> 2, tq = lane & 3;

    int nse = 0;
    const int* mfp = mf + b*32;
#pragma unroll
    for (int i2 = 0; i2 < 32; i2++) if (mfp[i2] & 1) nse = i2 + 1;

    const __half* kbase = kg + ((size_t)(b*TT)) * DD + h*64;
    const __half* vbase = vg + ((size_t)(b*TT)) * DD + h*64;

    const int lr = tid >> 3, lq = tid & 7;
    uint32_t lso = (uint32_t)((lr << 7) + (lq << 4));
    lso ^= (lso >> 3) & 0x70;

    auto issue_kv = [&](int s0, int stg) {
        const __half* ks = kbase + (size_t)s0 * DD;
        const __half* vs = vbase + (size_t)s0 * DD;
#pragma unroll
        for (int v = 0; v < 2; v++) {
            CPA(sK + stg*8192 + lso + v*4096, ks + (size_t)(lr + v*32)*DD + lq*8);
            CPA(sV + stg*8192 + lso + v*4096, vs + (size_t)(lr + v*32)*DD + lq*8);
        }
    };

    // prologue: 2 blocks in flight (3rd slot issued inside loop)
    issue_kv(0, 0); CPCOMMIT;
    if (nse > 1) issue_kv(64, 1);
    CPCOMMIT;

    {
        const __half* src = qg + ((size_t)(b*TT) + t0) * DD + h*64;
#pragma unroll
        for (int v = 0; v < 4; v++) {
            int p = tid + (v << 8);
            int t = p >> 3, dq = p & 7;
            uint32_t o = (uint32_t)(t*128 + dq*16); o ^= (o >> 3) & 0x70;
            *(uint4*)(base + o) = *(const uint4*)(src + (size_t)t*DD + dq*8);
        }
    }

    float mrow[2] = {-1e30f, -1e30f};
    float lrow[2] = {0.f, 0.f};
    float o[8][4];
#pragma unroll
    for (int ni = 0; ni < 8; ni++)
#pragma unroll
        for (int v = 0; v < 4; v++) o[ni][v] = 0.f;

    for (int i = 0; i < nse; i++) {
        // issue block i+2 into stage (i+2)%3 BEFORE waiting (deep prefetch)
        if (i + 2 < nse) issue_kv((i+2)*64, (i+2) % 3);
        CPCOMMIT;
        CPWAIT(2);               // groups: 2 prologue + (i+1) loop commits; ≤2 pending => block i ready
        __syncthreads();
        const int stg = i % 3;
        const uint32_t kS = sK + stg*8192;
        const uint32_t vS = sV + stg*8192;
        const int s0 = i * 64;

        float sa[8][4];
#pragma unroll
        for (int ni = 0; ni < 8; ni++)
#pragma unroll
            for (int v = 0; v < 4; v++) sa[ni][v] = 0.f;
#pragma unroll
        for (int kk = 0; kk < 4; kk++) {
            const int kb = kk*32 + ((lane >> 4) << 4);
            uint32_t a[4], b0[8], b1[8];
            {
                int row = wid*16 + (lane & 15);
                uint32_t oo = (uint32_t)(row*128 + kb); oo ^= (oo >> 3) & 0x70;
                ldsm4(a[0], a[1], a[2], a[3], sQ + oo);
            }
#pragma unroll
            for (int j = 0; j < 4; j++) {
                int row = j*16 + (lane & 15);
                uint32_t oo = (uint32_t)(row*128 + kb); oo ^= (oo >> 3) & 0x70;
                ldsm4(b0[2*j], b0[2*j+1], b1[2*j], b1[2*j+1], kS + oo);
            }
#pragma unroll
            for (int ni = 0; ni < 8; ni++) mma_f16(sa[ni], a, b0[ni], b1[ni]);
        }

        if (!(mfp[i] & 2)) {
            int tr0 = t0 + wid*16 + g;
            const uint32_t* mrow0 = mb + ((size_t)(b*TT) + tr0)*(TT/32) + (s0 >> 5);
            const uint32_t* mrow1 = mrow0 + 8*(TT/32);
            uint32_t w00 = mrow0[0], w01 = mrow0[1];
            uint32_t w10 = mrow1[0], w11 = mrow1[1];
#pragma unroll
            for (int ni = 0; ni < 8; ni++) {
#pragma unroll
                for (int v = 0; v < 4; v++) {
                    int sc = ni*8 + 2*tq + (v & 1);
                    uint32_t wsel = (v < 2) ? ((sc < 32) ? w00 : w01)
                                            : ((sc < 32) ? w10 : w11);
                    bool ok = (wsel >> (sc & 31)) & 1u;
                    if (!ok) sa[ni][v] = -1e30f;
                }
            }
        }

        uint32_t pp[8][2];
#pragma unroll
        for (int rh = 0; rh < 2; rh++) {
            float mx = -1e30f;
#pragma unroll
            for (int ni = 0; ni < 8; ni++)
                mx = fmaxf(mx, fmaxf(sa[ni][rh*2], sa[ni][rh*2+1]));
            mx = fmaxf(mx, __shfl_xor_sync(0xffffffffu, mx, 1));
            mx = fmaxf(mx, __shfl_xor_sync(0xffffffffu, mx, 2));
            float mn = fmaxf(mrow[rh], mx);
            float alpha = exp2f(mrow[rh] - mn);
            mrow[rh] = mn;
            float rs = 0.f;
#pragma unroll
            for (int ni = 0; ni < 8; ni++) {
                uint32_t ph = packh2(sa[ni][rh*2] - mn, sa[ni][rh*2+1] - mn);
                __half2 pe = h2exp2(*(__half2*)&ph);
                pp[ni][rh] = *(uint32_t*)&pe;
                float2 pf = __half22float2(pe);
                rs += pf.x + pf.y;
            }
            rs += __shfl_xor_sync(0xffffffffu, rs, 1);
            rs += __shfl_xor_sync(0xffffffffu, rs, 2);
            lrow[rh] = lrow[rh]*alpha + rs;
#pragma unroll
            for (int ni = 0; ni < 8; ni++) { o[ni][rh*2] *= alpha; o[ni][rh*2+1] *= alpha; }
        }

#pragma unroll
        for (int ni = 0; ni < 8; ni++) {
#pragma unroll
            for (int rh = 0; rh < 2; rh++) {
                int trow = wid*16 + g + rh*8;
                int scol = ni*8 + 2*tq;
                uint32_t oo = (uint32_t)(trow*128 + scol*2); oo ^= (oo >> 3) & 0x70;
                *(uint32_t*)(base + (sP - sb) + oo) = pp[ni][rh];
            }
        }
        __syncwarp();

#pragma unroll
        for (int kk = 0; kk < 4; kk++) {
            uint32_t a[4], b0[8], b1[8];
            {
                int row = wid*16 + (lane & 15);
                uint32_t oo = (uint32_t)(row*128 + kk*32 + ((lane >> 4) << 4));
                oo ^= (oo >> 3) & 0x70;
                ldsm4(a[0], a[1], a[2], a[3], sP + oo);
            }
#pragma unroll
            for (int j = 0; j < 4; j++) {
                int rs_ = kk*16 + (lane & 15);
                uint32_t oo = (uint32_t)(rs_*128 + j*32 + ((lane >> 4) << 4));
                oo ^= (oo >> 3) & 0x70;
                ldsm4t(b0[2*j], b1[2*j], b0[2*j+1], b1[2*j+1], vS + oo);
            }
#pragma unroll
            for (int ni = 0; ni < 8; ni++) mma_f16(o[ni], a, b0[ni], b1[ni]);
        }
        __syncthreads();   // all warps done reading stage i before iter i+1 overwrites stage (i+3)%3 == i%3
    }

#pragma unroll
    for (int rh = 0; rh < 2; rh++) {
        float inv = 1.0f / lrow[rh];
        int t = t0 + wid*16 + g + rh*8;
        size_t rb = ((size_t)(b*TT) + t) * DD;
#pragma unroll
        for (int ni = 0; ni < 8; ni++) {
            int col = h*64 + ni*8 + 2*tq;
            uint32_t hv = packh2(o[ni][rh*2] * inv, o[ni][rh*2+1] * inv);
            *(uint32_t*)(attH + rb + col) = hv;
        }
    }
}

// ================= launch =================
template<typename T>
static T* symaddr(const void* sym) {
    void* p = nullptr;
    cudaGetSymbolAddress(&p, sym);
    return (T*)p;
}

extern "C" void kernel_launch(void* const* d_in, const int* in_sizes, int n_in,
                              void* d_out, int out_size) {
    const float* x      = (const float*)d_in[0];
    const int*   mask   = (const int*)  d_in[1];
    const float* wq     = (const float*)d_in[2];
    const float* wk     = (const float*)d_in[3];
    const float* wv     = (const float*)d_in[4];
    const float* w_proj = (const float*)d_in[5];
    const float* b_proj = (const float*)d_in[6];
    const float* ln1_g  = (const float*)d_in[7];
    const float* ln1_b  = (const float*)d_in[8];
    const float* ln2_g  = (const float*)d_in[9];
    const float* ln2_b  = (const float*)d_in[10];
    const float* w1     = (const float*)d_in[11];
    const float* b1     = (const float*)d_in[12];
    const float* w2     = (const float*)d_in[13];
    const float* b2     = (const float*)d_in[14];
    float* out = (float*)d_out;

    __half* h16   = symaddr<__half>(g_h16);
    __half* qkv   = symaddr<__half>(g_qkv);
    __half* att   = symaddr<__half>(g_att);
    float*  x2_   = symaddr<float>(g_x2);
    __half* h216  = symaddr<__half>(g_h216);
    __half* ff    = symaddr<__half>(g_ff);
    __half* wqkvT = symaddr<__half>(g_wqkvT);
    __half* wpT   = symaddr<__half>(g_wpT);
    __half* w1T   = symaddr<__half>(g_w1T);
    __half* w2T   = symaddr<__half>(g_w2T);
    uint32_t* mb  = symaddr<uint32_t>(g_mb);
    int*    mf    = symaddr<int>(g_mf);
    float2* rt    = symaddr<float2>(g_rt);

    const int SMEM_MM = 3*32768 + 1024;   // 99328
    const int SMEM_FL = 81920 + 1024;     // 82944 (2 CTA/SM: 166KB < 228KB)
    cudaFuncSetAttribute(mm16<49>, cudaFuncAttributeMaxDynamicSharedMemorySize, SMEM_MM);
    cudaFuncSetAttribute(mm16<10>, cudaFuncAttributeMaxDynamicSharedMemorySize, SMEM_MM);
    cudaFuncSetAttribute(mm16<22>, cudaFuncAttributeMaxDynamicSharedMemorySize, SMEM_MM);
    cudaFuncSetAttribute(flash_kernel, cudaFuncAttributeMaxDynamicSharedMemorySize, SMEM_FL);

    // fused preprocessing: wtall + packmask + ropetab + LN1
    prep_kernel<<<17664, 256>>>(wq, wk, wv, w_proj, w1, w2,
                                wqkvT, wpT, w1T, w2T,
                                mask, mb, rt, x, ln1_g, ln1_b, h16);

    // fused QKV GEMM: RoPE (z<2) + q-scale incl. log2e (z==0), fp16 out
    mm16<49><<<dim3(DD/128, NROWS/128, 3), 256, SMEM_MM>>>(
        h16, wqkvT, nullptr, nullptr, nullptr, qkv, DD, DD,
        (long)DD*DD, (long)NROWS*DD, rt);

    // maskflags fills QKV tail wave (flash needs mf; QKV does not)
    maskflags_kernel<<<BB*32, 256>>>(mb, mf);

    // flash attention (exp2 domain, 3-stage KV pipeline)
    flash_kernel<<<dim3(TT/128, NBH), 256, SMEM_FL>>>(
        qkv, qkv + (size_t)NROWS*DD, qkv + 2*(size_t)NROWS*DD, mb, mf, att);

    // proj + bias + residual -> x2 (fp32)
    mm16<10><<<dim3(DD/128, NROWS/128), 256, SMEM_MM>>>(
        att, wpT, b_proj, x, x2_, nullptr, DD, DD, 0L, 0L, rt);

    // LN2 -> fp16
    ln16_kernel<<<NROWS, 256>>>(x2_, ln2_g, ln2_b, h216);

    // MLP1: bias + relu -> fp16
    mm16<22><<<dim3(FF/128, NROWS/128), 256, SMEM_MM>>>(
        h216, w1T, b1, nullptr, nullptr, ff, FF, DD, 0L, 0L, rt);

    // MLP2: bias + residual -> out (fp32)
    mm16<10><<<dim3(DD/128, NROWS/128), 256, SMEM_MM>>>(
        ff, w2T, b2, x2_, out, nullptr, DD, FF, 0L, 0L, rt);
}

// round 16
// speedup vs baseline: 1.0133x; 1.0133x over previous
#include <cuda_runtime.h>
#include <cuda_fp16.h>
#include <cstdint>
#include <math.h>

#define BB 2
#define TT 2048
#define DD 1024
#define HH 16
#define FF 4096
#define NROWS (BB*TT)
#define NBH (BB*HH)

// ================= scratch =================
__device__ __align__(256) __half  g_h16 [NROWS*DD];
__device__ __align__(256) __half  g_qkv [3*(size_t)NROWS*DD];
__device__ __align__(256) __half  g_att [NROWS*DD];
__device__ __align__(256) float   g_x2  [NROWS*DD];
__device__ __align__(256) __half  g_h216[NROWS*DD];
__device__ __align__(256) __half  g_ff  [(size_t)NROWS*FF];
__device__ __align__(256) __half  g_wqkvT[3*(size_t)DD*DD];
__device__ __align__(256) __half  g_wpT [(size_t)DD*DD];
__device__ __align__(256) __half  g_w1T [(size_t)FF*DD];
__device__ __align__(256) __half  g_w2T [(size_t)DD*FF];
__device__ __align__(256) uint32_t g_mb [BB*TT*(TT/32)];
__device__ __align__(256) int      g_mf [BB*32];
__device__ __align__(256) float2  g_rt  [TT*32];

// scale folded into Q: 1/sqrt(64) * log2(e)  (softmax done in exp2 domain)
#define QSCALE_LOG2E 0.18033688011112042f

// ================= helpers =================
__device__ __forceinline__ uint32_t smem_u32(const void* p) {
    uint32_t a;
    asm("{ .reg .u64 t; cvta.to.shared.u64 t, %1; cvt.u32.u64 %0, t; }" : "=r"(a) : "l"(p));
    return a;
}
#define CPA(dst, src) \
    asm volatile("cp.async.cg.shared.global [%0], [%1], 16;" :: "r"(dst), "l"(src) : "memory")
#define CPCOMMIT asm volatile("cp.async.commit_group;" ::: "memory")
#define CPWAIT(n) asm volatile("cp.async.wait_group %0;" :: "n"(n) : "memory")

__device__ __forceinline__ void ldsm4(uint32_t& r0, uint32_t& r1, uint32_t& r2, uint32_t& r3, uint32_t a) {
    asm volatile("ldmatrix.sync.aligned.m8n8.x4.shared.b16 {%0,%1,%2,%3}, [%4];"
        : "=r"(r0), "=r"(r1), "=r"(r2), "=r"(r3) : "r"(a));
}
__device__ __forceinline__ void ldsm4t(uint32_t& r0, uint32_t& r1, uint32_t& r2, uint32_t& r3, uint32_t a) {
    asm volatile("ldmatrix.sync.aligned.m8n8.x4.trans.shared.b16 {%0,%1,%2,%3}, [%4];"
        : "=r"(r0), "=r"(r1), "=r"(r2), "=r"(r3) : "r"(a));
}
__device__ __forceinline__ void mma_f16(float* c, const uint32_t* a, uint32_t b0, uint32_t b1) {
    asm volatile("mma.sync.aligned.m16n8k16.row.col.f32.f16.f16.f32 "
        "{%0,%1,%2,%3}, {%4,%5,%6,%7}, {%8,%9}, {%0,%1,%2,%3};"
        : "+f"(c[0]), "+f"(c[1]), "+f"(c[2]), "+f"(c[3])
        : "r"(a[0]), "r"(a[1]), "r"(a[2]), "r"(a[3]), "r"(b0), "r"(b1));
}
__device__ __forceinline__ uint32_t packh2(float a, float b) {
    __half2 h = __floats2half2_rn(a, b);
    return *(uint32_t*)&h;
}

// ================= uber preprocessing kernel =================
// grid ranges: [0,12288) wtall  [12288,13312) packmask  [13312,13568) ropetab
//              [13568,17664) LN1
__global__ void __launch_bounds__(256) prep_kernel(
        const float* __restrict__ wq, const float* __restrict__ wk,
        const float* __restrict__ wv, const float* __restrict__ wp,
        const float* __restrict__ w1, const float* __restrict__ w2,
        __half* __restrict__ oqkv, __half* __restrict__ op,
        __half* __restrict__ o1, __half* __restrict__ o2,
        const int* __restrict__ mask, uint32_t* __restrict__ mb,
        float2* __restrict__ rt,
        const float* __restrict__ x, const float* __restrict__ g1,
        const float* __restrict__ b1v, __half* __restrict__ h16out) {
    __shared__ float shm[32*33];
    int bid = blockIdx.x;
    int tid = threadIdx.x;

    if (bid < 12288) {
        const float* W; __half* out; int K, N, tile;
        if (bid < 3072)      { int w = bid >> 10; W = (w==0)?wq:((w==1)?wk:wv);
                               out = oqkv + (size_t)w*DD*DD; K = DD; N = DD; tile = bid & 1023; }
        else if (bid < 4096) { W = wp; out = op; K = DD; N = DD; tile = bid - 3072; }
        else if (bid < 8192) { W = w1; out = o1; K = DD; N = FF; tile = bid - 4096; }
        else                 { W = w2; out = o2; K = FF; N = DD; tile = bid - 8192; }
        int ntx = N >> 5;
        int n0 = (tile % ntx) << 5, k0 = (tile / ntx) << 5;
        int tx = tid & 31, ty = tid >> 5;
#pragma unroll
        for (int r = 0; r < 4; r++)
            shm[(ty + 8*r)*33 + tx] = W[(size_t)(k0 + ty + 8*r) * N + n0 + tx];
        __syncthreads();
#pragma unroll
        for (int r = 0; r < 4; r++)
            out[(size_t)(n0 + ty + 8*r) * K + k0 + tx] = __float2half_rn(shm[tx*33 + ty + 8*r]);
    } else if (bid < 13312) {
        int wi = (bid - 12288) * 256 + tid;
        const int4* p = (const int4*)(mask + (size_t)wi * 32);
        uint32_t w = 0;
#pragma unroll
        for (int j = 0; j < 8; j++) {
            int4 v = p[j];
            w |= (uint32_t)(v.x != 0) << (j*4 + 0);
            w |= (uint32_t)(v.y != 0) << (j*4 + 1);
            w |= (uint32_t)(v.z != 0) << (j*4 + 2);
            w |= (uint32_t)(v.w != 0) << (j*4 + 3);
        }
        mb[wi] = w;
    } else if (bid < 13568) {
        int idx = (bid - 13312) * 256 + tid;
        int t = idx >> 5, pi = idx & 31;
        float theta = expf(-((2.0f * pi) / 64.0f) * logf(10000.0f));
        float ang = (float)t * theta;
        rt[idx] = make_float2(cosf(ang), sinf(ang));
    } else {
        int row = bid - 13568;
        const float4 f = ((const float4*)(x + (size_t)row * DD))[tid];
        int wid = tid >> 5, lane = tid & 31;

        float s = f.x + f.y + f.z + f.w;
#pragma unroll
        for (int o = 16; o; o >>= 1) s += __shfl_xor_sync(~0u, s, o);
        if (lane == 0) shm[wid] = s;
        __syncthreads();
        s = shm[lane & 7];
#pragma unroll
        for (int o = 4; o; o >>= 1) s += __shfl_xor_sync(~0u, s, o);
        float mean = s * (1.0f / DD);

        float dx = f.x - mean, dy = f.y - mean, dz = f.z - mean, dw = f.w - mean;
        float v = dx*dx + dy*dy + dz*dz + dw*dw;
#pragma unroll
        for (int o = 16; o; o >>= 1) v += __shfl_xor_sync(~0u, v, o);
        __syncthreads();
        if (lane == 0) shm[wid] = v;
        __syncthreads();
        v = shm[lane & 7];
#pragma unroll
        for (int o = 4; o; o >>= 1) v += __shfl_xor_sync(~0u, v, o);
        float inv = rsqrtf(v * (1.0f / DD) + 1e-5f);

        const float4 g4 = ((const float4*)g1)[tid];
        const float4 b4 = ((const float4*)b1v)[tid];
        uint2 st;
        st.x = packh2(dx*inv*g4.x + b4.x, dy*inv*g4.y + b4.y);
        st.y = packh2(dz*inv*g4.z + b4.z, dw*inv*g4.w + b4.w);
        *(uint2*)(h16out + (size_t)row * DD + tid*4) = st;
    }
}

// ================= LayerNorm -> fp16 (standalone for LN2) =================
__global__ void ln16_kernel(const float* __restrict__ x, const float* __restrict__ g,
                            const float* __restrict__ b, __half* __restrict__ out) {
    int row = blockIdx.x;
    int tid = threadIdx.x;
    const float4 f = ((const float4*)(x + (size_t)row * DD))[tid];
    __shared__ float sw[8];
    int wid = tid >> 5, lane = tid & 31;

    float s = f.x + f.y + f.z + f.w;
#pragma unroll
    for (int o = 16; o; o >>= 1) s += __shfl_xor_sync(~0u, s, o);
    if (lane == 0) sw[wid] = s;
    __syncthreads();
    s = sw[lane & 7];
#pragma unroll
    for (int o = 4; o; o >>= 1) s += __shfl_xor_sync(~0u, s, o);
    float mean = s * (1.0f / DD);

    float dx = f.x - mean, dy = f.y - mean, dz = f.z - mean, dw = f.w - mean;
    float v = dx*dx + dy*dy + dz*dz + dw*dw;
#pragma unroll
    for (int o = 16; o; o >>= 1) v += __shfl_xor_sync(~0u, v, o);
    __syncthreads();
    if (lane == 0) sw[wid] = v;
    __syncthreads();
    v = sw[lane & 7];
#pragma unroll
    for (int o = 4; o; o >>= 1) v += __shfl_xor_sync(~0u, v, o);
    float inv = rsqrtf(v * (1.0f / DD) + 1e-5f);

    const float4 g4 = ((const float4*)g)[tid];
    const float4 b4 = ((const float4*)b)[tid];
    uint2 st;
    st.x = packh2(dx*inv*g4.x + b4.x, dy*inv*g4.y + b4.y);
    st.y = packh2(dz*inv*g4.z + b4.z, dw*inv*g4.w + b4.w);
    *(uint2*)(out + (size_t)row * DD + tid*4) = st;
}

// ================= per-(b, key-block) all/any flags (reads packed mb) ==========
__global__ void maskflags_kernel(const uint32_t* __restrict__ mb, int* __restrict__ mf) {
    int bs = blockIdx.x;
    int b = bs >> 5, sblk = bs & 31;
    uint32_t av = 0xFFFFFFFFu, ov = 0u;
    for (int t = threadIdx.x; t < TT; t += 256) {
        const uint32_t* p = mb + ((size_t)(b*TT) + t)*(TT/32) + sblk*2;
        uint32_t w0 = p[0], w1 = p[1];
        av &= (w0 & w1); ov |= (w0 | w1);
    }
    __shared__ uint32_t sa[8], so[8];
#pragma unroll
    for (int o = 16; o; o >>= 1) {
        av &= __shfl_xor_sync(~0u, av, o);
        ov |= __shfl_xor_sync(~0u, ov, o);
    }
    int w = threadIdx.x >> 5;
    if ((threadIdx.x & 31) == 0) { sa[w] = av; so[w] = ov; }
    __syncthreads();
    if (threadIdx.x == 0) {
        av = 0xFFFFFFFFu; ov = 0u;
#pragma unroll
        for (int i = 0; i < 8; i++) { av &= sa[i]; ov |= so[i]; }
        mf[bs] = ((av == 0xFFFFFFFFu) ? 2 : 0) | (ov ? 1 : 0);
    }
}

// ================= mma.sync fp16 GEMM (128x128, 3-stage, 2 CTA/SM) — proven ====
// EPI bits: 1=ROPE(z<2), 2=BIAS, 4=RELU, 8=RES, 16=F16OUT, 32=QSCALE(z==0)
template<int EPI>
__global__ void __launch_bounds__(256, 2) mm16(
        const __half* __restrict__ A, const __half* __restrict__ B0,
        const float* __restrict__ bias, const float* __restrict__ res,
        float* __restrict__ outF, __half* __restrict__ outH0,
        int N, int K, long zsB, long zsC, const float2* __restrict__ rt) {
    extern __shared__ char smem_raw[];
    const uint32_t sbr = smem_u32(smem_raw);
    const uint32_t sb = (sbr + 1023) & ~1023u;

    const int tid = threadIdx.x, wid = tid >> 5, lane = tid & 31;
    const int wm = wid >> 1, wn = wid & 1;
    const int m0 = blockIdx.y << 7, n0 = blockIdx.x << 7;
    const int NC = K >> 6;

    const __half* Bw = B0 + (size_t)blockIdx.z * zsB;
    __half* outH = outH0 + (size_t)blockIdx.z * zsC;

    const __half* Ag = A  + (size_t)m0 * K;
    const __half* Bg = Bw + (size_t)n0 * K;

    const int rq_r = tid >> 3, rq_q = tid & 7;
    const __half* agp = Ag + (size_t)rq_r * K + (rq_q << 3);
    const __half* bgp = Bg + (size_t)rq_r * K + (rq_q << 3);
    uint32_t so = (uint32_t)((rq_r << 7) + (rq_q << 4));
    so ^= (so >> 3) & 0x70;
    const size_t rowstep = (size_t)32 * K;

    auto issue_load = [&](int c, int stg) {
        uint32_t sA = sb + stg * 32768;
#pragma unroll
        for (int v = 0; v < 4; v++) {
            CPA(sA + so + v*4096,         agp + (size_t)c*64 + v*rowstep);
            CPA(sA + 16384 + so + v*4096, bgp + (size_t)c*64 + v*rowstep);
        }
    };

    float acc[2][8][4];
#pragma unroll
    for (int mi = 0; mi < 2; mi++)
#pragma unroll
        for (int ni = 0; ni < 8; ni++)
#pragma unroll
            for (int v = 0; v < 4; v++) acc[mi][ni][v] = 0.f;

#pragma unroll
    for (int s = 0; s < 3; s++) { issue_load(s, s); CPCOMMIT; }

    for (int c = 0; c < NC; c++) {
        CPWAIT(2);
        __syncthreads();
        int stg = c % 3;
        uint32_t sA = sb + stg * 32768;
        uint32_t sB = sA + 16384;
#pragma unroll
        for (int kk = 0; kk < 4; kk++) {
            uint32_t a[2][4], b0[8], b1[8];
            const int kb = kk*32 + ((lane >> 4) << 4);
#pragma unroll
            for (int mi = 0; mi < 2; mi++) {
                int row = wm*32 + mi*16 + (lane & 15);
                uint32_t o = (uint32_t)(row*128 + kb); o ^= (o >> 3) & 0x70;
                ldsm4(a[mi][0], a[mi][1], a[mi][2], a[mi][3], sA + o);
            }
#pragma unroll
            for (int j = 0; j < 4; j++) {
                int row = wn*64 + j*16 + (lane & 15);
                uint32_t o = (uint32_t)(row*128 + kb); o ^= (o >> 3) & 0x70;
                ldsm4(b0[2*j], b0[2*j+1], b1[2*j], b1[2*j+1], sB + o);
            }
#pragma unroll
            for (int mi = 0; mi < 2; mi++)
#pragma unroll
                for (int ni = 0; ni < 8; ni++)
                    mma_f16(acc[mi][ni], a[mi], b0[ni], b1[ni]);
        }
        __syncthreads();
        if (c + 3 < NC) issue_load(c + 3, stg);
        CPCOMMIT;
    }
    CPWAIT(0);

    // epilogue
    const int g = lane >> 2, tq = lane & 3;
    const bool doRope = (EPI & 1) && (blockIdx.z < 2);
    const bool doQs   = (EPI & 32) && (blockIdx.z == 0);
#pragma unroll
    for (int mi = 0; mi < 2; mi++) {
#pragma unroll
        for (int ni = 0; ni < 8; ni++) {
            const int colb = n0 + wn*64 + ni*8 + 2*tq;
            float2 bv = make_float2(0.f, 0.f);
            if (EPI & 2) bv = *(const float2*)(bias + colb);
#pragma unroll
            for (int rh = 0; rh < 2; rh++) {
                int row = m0 + wm*32 + mi*16 + g + rh*8;
                float v0 = acc[mi][ni][rh*2], v1 = acc[mi][ni][rh*2+1];
                if (EPI & 2) { v0 += bv.x; v1 += bv.y; }
                if (EPI & 4) { v0 = fmaxf(v0, 0.f); v1 = fmaxf(v1, 0.f); }
                if (doRope) {
                    int t = row & (TT-1);
                    int pi = (colb & 63) >> 1;
                    float2 cs = rt[t*32 + pi];
                    float nv0 = v0*cs.x - v1*cs.y;
                    float nv1 = v0*cs.y + v1*cs.x;
                    v0 = nv0; v1 = nv1;
                }
                if (doQs) { v0 *= QSCALE_LOG2E; v1 *= QSCALE_LOG2E; }
                if (EPI & 8) {
                    float2 rv = *(const float2*)(res + (size_t)row*N + colb);
                    v0 += rv.x; v1 += rv.y;
                }
                if (EPI & 16) {
                    uint32_t hv = packh2(v0, v1);
                    *(uint32_t*)(outH + (size_t)row*N + colb) = hv;
                } else {
                    *(float2*)(outF + (size_t)row*N + colb) = make_float2(v0, v1);
                }
            }
        }
    }
}

// ================= flash attention: exp2 fp16x2, 2-stage (R10 proven best) ======
__global__ void __launch_bounds__(256, 2) flash_kernel(
        const __half* __restrict__ qg, const __half* __restrict__ kg, const __half* __restrict__ vg,
        const uint32_t* __restrict__ mb, const int* __restrict__ mf,
        __half* __restrict__ attH) {
    extern __shared__ char smem_raw[];
    const uint32_t sbr = smem_u32(smem_raw);
    const uint32_t sb = (sbr + 1023) & ~1023u;
    char* base = smem_raw + (int)(sb - sbr);

    const uint32_t sQ = sb, sK = sb + 16384, sV = sb + 32768, sP = sb + 49152;

    int bh = blockIdx.y, b = bh >> 4, h = bh & 15;
    int t0 = blockIdx.x << 7;
    int tid = threadIdx.x, wid = tid >> 5, lane = tid & 31;
    int g = lane >> 2, tq = lane & 3;

    int nse = 0;
    const int* mfp = mf + b*32;
#pragma unroll
    for (int i2 = 0; i2 < 32; i2++) if (mfp[i2] & 1) nse = i2 + 1;

    const __half* kbase = kg + ((size_t)(b*TT)) * DD + h*64;
    const __half* vbase = vg + ((size_t)(b*TT)) * DD + h*64;

    const int lr = tid >> 3, lq = tid & 7;
    uint32_t lso = (uint32_t)((lr << 7) + (lq << 4));
    lso ^= (lso >> 3) & 0x70;

    auto issue_kv = [&](int s0, int stg) {
        const __half* ks = kbase + (size_t)s0 * DD;
        const __half* vs = vbase + (size_t)s0 * DD;
#pragma unroll
        for (int v = 0; v < 2; v++) {
            CPA(sK + stg*8192 + lso + v*4096, ks + (size_t)(lr + v*32)*DD + lq*8);
            CPA(sV + stg*8192 + lso + v*4096, vs + (size_t)(lr + v*32)*DD + lq*8);
        }
    };

    issue_kv(0, 0); CPCOMMIT;

    {
        const __half* src = qg + ((size_t)(b*TT) + t0) * DD + h*64;
#pragma unroll
        for (int v = 0; v < 4; v++) {
            int p = tid + (v << 8);
            int t = p >> 3, dq = p & 7;
            uint32_t o = (uint32_t)(t*128 + dq*16); o ^= (o >> 3) & 0x70;
            *(uint4*)(base + o) = *(const uint4*)(src + (size_t)t*DD + dq*8);
        }
    }

    float mrow[2] = {-1e30f, -1e30f};
    float lrow[2] = {0.f, 0.f};
    float o[8][4];
#pragma unroll
    for (int ni = 0; ni < 8; ni++)
#pragma unroll
        for (int v = 0; v < 4; v++) o[ni][v] = 0.f;

    for (int i = 0; i < nse; i++) {
        if (i + 1 < nse) { issue_kv((i+1)*64, (i+1) & 1); CPCOMMIT; CPWAIT(1); }
        else             { CPWAIT(0); }
        __syncthreads();
        const uint32_t kS = sK + (i & 1)*8192;
        const uint32_t vS = sV + (i & 1)*8192;
        const int s0 = i * 64;

        float sa[8][4];
#pragma unroll
        for (int ni = 0; ni < 8; ni++)
#pragma unroll
            for (int v = 0; v < 4; v++) sa[ni][v] = 0.f;
#pragma unroll
        for (int kk = 0; kk < 4; kk++) {
            const int kb = kk*32 + ((lane >> 4) << 4);
            uint32_t a[4], b0[8], b1[8];
            {
                int row = wid*16 + (lane & 15);
                uint32_t oo = (uint32_t)(row*128 + kb); oo ^= (oo >> 3) & 0x70;
                ldsm4(a[0], a[1], a[2], a[3], sQ + oo);
            }
#pragma unroll
            for (int j = 0; j < 4; j++) {
                int row = j*16 + (lane & 15);
                uint32_t oo = (uint32_t)(row*128 + kb); oo ^= (oo >> 3) & 0x70;
                ldsm4(b0[2*j], b0[2*j+1], b1[2*j], b1[2*j+1], kS + oo);
            }
#pragma unroll
            for (int ni = 0; ni < 8; ni++) mma_f16(sa[ni], a, b0[ni], b1[ni]);
        }

        if (!(mfp[i] & 2)) {
            int tr0 = t0 + wid*16 + g;
            const uint32_t* mrow0 = mb + ((size_t)(b*TT) + tr0)*(TT/32) + (s0 >> 5);
            const uint32_t* mrow1 = mrow0 + 8*(TT/32);
            uint32_t w00 = mrow0[0], w01 = mrow0[1];
            uint32_t w10 = mrow1[0], w11 = mrow1[1];
#pragma unroll
            for (int ni = 0; ni < 8; ni++) {
#pragma unroll
                for (int v = 0; v < 4; v++) {
                    int sc = ni*8 + 2*tq + (v & 1);
                    uint32_t wsel = (v < 2) ? ((sc < 32) ? w00 : w01)
                                            : ((sc < 32) ? w10 : w11);
                    bool ok = (wsel >> (sc & 31)) & 1u;
                    if (!ok) sa[ni][v] = -1e30f;
                }
            }
        }

        uint32_t pp[8][2];
#pragma unroll
        for (int rh = 0; rh < 2; rh++) {
            float mx = -1e30f;
#pragma unroll
            for (int ni = 0; ni < 8; ni++)
                mx = fmaxf(mx, fmaxf(sa[ni][rh*2], sa[ni][rh*2+1]));
            mx = fmaxf(mx, __shfl_xor_sync(0xffffffffu, mx, 1));
            mx = fmaxf(mx, __shfl_xor_sync(0xffffffffu, mx, 2));
            float mn = fmaxf(mrow[rh], mx);
            float alpha = exp2f(mrow[rh] - mn);
            mrow[rh] = mn;
            float rs = 0.f;
#pragma unroll
            for (int ni = 0; ni < 8; ni++) {
                uint32_t ph = packh2(sa[ni][rh*2] - mn, sa[ni][rh*2+1] - mn);
                __half2 pe = h2exp2(*(__half2*)&ph);
                pp[ni][rh] = *(uint32_t*)&pe;
                float2 pf = __half22float2(pe);
                rs += pf.x + pf.y;
            }
            rs += __shfl_xor_sync(0xffffffffu, rs, 1);
            rs += __shfl_xor_sync(0xffffffffu, rs, 2);
            lrow[rh] = lrow[rh]*alpha + rs;
#pragma unroll
            for (int ni = 0; ni < 8; ni++) { o[ni][rh*2] *= alpha; o[ni][rh*2+1] *= alpha; }
        }

#pragma unroll
        for (int ni = 0; ni < 8; ni++) {
#pragma unroll
            for (int rh = 0; rh < 2; rh++) {
                int trow = wid*16 + g + rh*8;
                int scol = ni*8 + 2*tq;
                uint32_t oo = (uint32_t)(trow*128 + scol*2); oo ^= (oo >> 3) & 0x70;
                *(uint32_t*)(base + (sP - sb) + oo) = pp[ni][rh];
            }
        }
        __syncwarp();

#pragma unroll
        for (int kk = 0; kk < 4; kk++) {
            uint32_t a[4], b0[8], b1[8];
            {
                int row = wid*16 + (lane & 15);
                uint32_t oo = (uint32_t)(row*128 + kk*32 + ((lane >> 4) << 4));
                oo ^= (oo >> 3) & 0x70;
                ldsm4(a[0], a[1], a[2], a[3], sP + oo);
            }
#pragma unroll
            for (int j = 0; j < 4; j++) {
                int rs_ = kk*16 + (lane & 15);
                uint32_t oo = (uint32_t)(rs_*128 + j*32 + ((lane >> 4) << 4));
                oo ^= (oo >> 3) & 0x70;
                ldsm4t(b0[2*j], b1[2*j], b0[2*j+1], b1[2*j+1], vS + oo);
            }
#pragma unroll
            for (int ni = 0; ni < 8; ni++) mma_f16(o[ni], a, b0[ni], b1[ni]);
        }
        __syncthreads();
    }

#pragma unroll
    for (int rh = 0; rh < 2; rh++) {
        float inv = 1.0f / lrow[rh];
        int t = t0 + wid*16 + g + rh*8;
        size_t rb = ((size_t)(b*TT) + t) * DD;
#pragma unroll
        for (int ni = 0; ni < 8; ni++) {
            int col = h*64 + ni*8 + 2*tq;
            uint32_t hv = packh2(o[ni][rh*2] * inv, o[ni][rh*2+1] * inv);
            *(uint32_t*)(attH + rb + col) = hv;
        }
    }
}

// ================= launch =================
template<typename T>
static T* symaddr(const void* sym) {
    void* p = nullptr;
    cudaGetSymbolAddress(&p, sym);
    return (T*)p;
}

extern "C" void kernel_launch(void* const* d_in, const int* in_sizes, int n_in,
                              void* d_out, int out_size) {
    const float* x      = (const float*)d_in[0];
    const int*   mask   = (const int*)  d_in[1];
    const float* wq     = (const float*)d_in[2];
    const float* wk     = (const float*)d_in[3];
    const float* wv     = (const float*)d_in[4];
    const float* w_proj = (const float*)d_in[5];
    const float* b_proj = (const float*)d_in[6];
    const float* ln1_g  = (const float*)d_in[7];
    const float* ln1_b  = (const float*)d_in[8];
    const float* ln2_g  = (const float*)d_in[9];
    const float* ln2_b  = (const float*)d_in[10];
    const float* w1     = (const float*)d_in[11];
    const float* b1     = (const float*)d_in[12];
    const float* w2     = (const float*)d_in[13];
    const float* b2     = (const float*)d_in[14];
    float* out = (float*)d_out;

    __half* h16   = symaddr<__half>(g_h16);
    __half* qkv   = symaddr<__half>(g_qkv);
    __half* att   = symaddr<__half>(g_att);
    float*  x2_   = symaddr<float>(g_x2);
    __half* h216  = symaddr<__half>(g_h216);
    __half* ff    = symaddr<__half>(g_ff);
    __half* wqkvT = symaddr<__half>(g_wqkvT);
    __half* wpT   = symaddr<__half>(g_wpT);
    __half* w1T   = symaddr<__half>(g_w1T);
    __half* w2T   = symaddr<__half>(g_w2T);
    uint32_t* mb  = symaddr<uint32_t>(g_mb);
    int*    mf    = symaddr<int>(g_mf);
    float2* rt    = symaddr<float2>(g_rt);

    const int SMEM_MM = 3*32768 + 1024;   // 99328
    const int SMEM_FL = 4*16384 + 1024;   // 66560
    cudaFuncSetAttribute(mm16<49>, cudaFuncAttributeMaxDynamicSharedMemorySize, SMEM_MM);
    cudaFuncSetAttribute(mm16<10>, cudaFuncAttributeMaxDynamicSharedMemorySize, SMEM_MM);
    cudaFuncSetAttribute(mm16<22>, cudaFuncAttributeMaxDynamicSharedMemorySize, SMEM_MM);
    cudaFuncSetAttribute(flash_kernel, cudaFuncAttributeMaxDynamicSharedMemorySize, SMEM_FL);

    // fused preprocessing: wtall + packmask + ropetab + LN1
    prep_kernel<<<17664, 256>>>(wq, wk, wv, w_proj, w1, w2,
                                wqkvT, wpT, w1T, w2T,
                                mask, mb, rt, x, ln1_g, ln1_b, h16);
    maskflags_kernel<<<BB*32, 256>>>(mb, mf);

    // fused QKV GEMM: RoPE (z<2) + q-scale incl. log2e (z==0), fp16 out
    mm16<49><<<dim3(DD/128, NROWS/128, 3), 256, SMEM_MM>>>(
        h16, wqkvT, nullptr, nullptr, nullptr, qkv, DD, DD,
        (long)DD*DD, (long)NROWS*DD, rt);

    // flash attention (exp2 domain)
    flash_kernel<<<dim3(TT/128, NBH), 256, SMEM_FL>>>(
        qkv, qkv + (size_t)NROWS*DD, qkv + 2*(size_t)NROWS*DD, mb, mf, att);

    // proj + bias + residual -> x2 (fp32)
    mm16<10><<<dim3(DD/128, NROWS/128), 256, SMEM_MM>>>(
        att, wpT, b_proj, x, x2_, nullptr, DD, DD, 0L, 0L, rt);

    // LN2 -> fp16
    ln16_kernel<<<NROWS, 256>>>(x2_, ln2_g, ln2_b, h216);

    // MLP1: bias + relu -> fp16
    mm16<22><<<dim3(FF/128, NROWS/128), 256, SMEM_MM>>>(
        h216, w1T, b1, nullptr, nullptr, ff, FF, DD, 0L, 0L, rt);

    // MLP2: bias + residual -> out (fp32)
    mm16<10><<<dim3(DD/128, NROWS/128), 256, SMEM_MM>>>(
        ff, w2T, b2, x2_, out, nullptr, DD, FF, 0L, 0L, rt);
}

// round 17
// speedup vs baseline: 1.0514x; 1.0376x over previous
#include <cuda_runtime.h>
#include <cuda_fp16.h>
#include <cstdint>
#include <math.h>

#define BB 2
#define TT 2048
#define DD 1024
#define HH 16
#define FF 4096
#define NROWS (BB*TT)
#define NBH (BB*HH)

// ================= scratch =================
__device__ __align__(256) __half  g_h16 [NROWS*DD];
__device__ __align__(256) __half  g_qkv [3*(size_t)NROWS*DD];
__device__ __align__(256) __half  g_att [NROWS*DD];
__device__ __align__(256) float   g_x2  [NROWS*DD];
__device__ __align__(256) __half  g_h216[NROWS*DD];
__device__ __align__(256) __half  g_ff  [(size_t)NROWS*FF];
__device__ __align__(256) __half  g_wqkvT[3*(size_t)DD*DD];
__device__ __align__(256) __half  g_wpT [(size_t)DD*DD];
__device__ __align__(256) __half  g_w1T [(size_t)FF*DD];
__device__ __align__(256) __half  g_w2T [(size_t)DD*FF];
__device__ __align__(256) uint32_t g_mb [BB*TT*(TT/32)];
__device__ __align__(256) int      g_mf [BB*32];
__device__ __align__(256) float2  g_rt  [TT*32];

// scale folded into Q: 1/sqrt(64) * log2(e)  (softmax done in exp2 domain)
#define QSCALE_LOG2E 0.18033688011112042f

// ================= helpers =================
__device__ __forceinline__ uint32_t smem_u32(const void* p) {
    uint32_t a;
    asm("{ .reg .u64 t; cvta.to.shared.u64 t, %1; cvt.u32.u64 %0, t; }" : "=r"(a) : "l"(p));
    return a;
}
#define CPA(dst, src) \
    asm volatile("cp.async.cg.shared.global [%0], [%1], 16;" :: "r"(dst), "l"(src) : "memory")
#define CPCOMMIT asm volatile("cp.async.commit_group;" ::: "memory")
#define CPWAIT(n) asm volatile("cp.async.wait_group %0;" :: "n"(n) : "memory")

__device__ __forceinline__ void ldsm4(uint32_t& r0, uint32_t& r1, uint32_t& r2, uint32_t& r3, uint32_t a) {
    asm volatile("ldmatrix.sync.aligned.m8n8.x4.shared.b16 {%0,%1,%2,%3}, [%4];"
        : "=r"(r0), "=r"(r1), "=r"(r2), "=r"(r3) : "r"(a));
}
__device__ __forceinline__ void ldsm4t(uint32_t& r0, uint32_t& r1, uint32_t& r2, uint32_t& r3, uint32_t a) {
    asm volatile("ldmatrix.sync.aligned.m8n8.x4.trans.shared.b16 {%0,%1,%2,%3}, [%4];"
        : "=r"(r0), "=r"(r1), "=r"(r2), "=r"(r3) : "r"(a));
}
__device__ __forceinline__ void mma_f16(float* c, const uint32_t* a, uint32_t b0, uint32_t b1) {
    asm volatile("mma.sync.aligned.m16n8k16.row.col.f32.f16.f16.f32 "
        "{%0,%1,%2,%3}, {%4,%5,%6,%7}, {%8,%9}, {%0,%1,%2,%3};"
        : "+f"(c[0]), "+f"(c[1]), "+f"(c[2]), "+f"(c[3])
        : "r"(a[0]), "r"(a[1]), "r"(a[2]), "r"(a[3]), "r"(b0), "r"(b1));
}
__device__ __forceinline__ uint32_t packh2(float a, float b) {
    __half2 h = __floats2half2_rn(a, b);
    return *(uint32_t*)&h;
}

// ================= uber preprocessing kernel =================
// grid ranges: [0,12288) wtall  [12288,13312) packmask  [13312,13568) ropetab
//              [13568,17664) LN1
__global__ void __launch_bounds__(256) prep_kernel(
        const float* __restrict__ wq, const float* __restrict__ wk,
        const float* __restrict__ wv, const float* __restrict__ wp,
        const float* __restrict__ w1, const float* __restrict__ w2,
        __half* __restrict__ oqkv, __half* __restrict__ op,
        __half* __restrict__ o1, __half* __restrict__ o2,
        const int* __restrict__ mask, uint32_t* __restrict__ mb,
        float2* __restrict__ rt,
        const float* __restrict__ x, const float* __restrict__ g1,
        const float* __restrict__ b1v, __half* __restrict__ h16out) {
    __shared__ float shm[32*33];
    int bid = blockIdx.x;
    int tid = threadIdx.x;

    if (bid < 12288) {
        const float* W; __half* out; int K, N, tile;
        if (bid < 3072)      { int w = bid >> 10; W = (w==0)?wq:((w==1)?wk:wv);
                               out = oqkv + (size_t)w*DD*DD; K = DD; N = DD; tile = bid & 1023; }
        else if (bid < 4096) { W = wp; out = op; K = DD; N = DD; tile = bid - 3072; }
        else if (bid < 8192) { W = w1; out = o1; K = DD; N = FF; tile = bid - 4096; }
        else                 { W = w2; out = o2; K = FF; N = DD; tile = bid - 8192; }
        int ntx = N >> 5;
        int n0 = (tile % ntx) << 5, k0 = (tile / ntx) << 5;
        int tx = tid & 31, ty = tid >> 5;
#pragma unroll
        for (int r = 0; r < 4; r++)
            shm[(ty + 8*r)*33 + tx] = W[(size_t)(k0 + ty + 8*r) * N + n0 + tx];
        __syncthreads();
#pragma unroll
        for (int r = 0; r < 4; r++)
            out[(size_t)(n0 + ty + 8*r) * K + k0 + tx] = __float2half_rn(shm[tx*33 + ty + 8*r]);
    } else if (bid < 13312) {
        int wi = (bid - 12288) * 256 + tid;
        const int4* p = (const int4*)(mask + (size_t)wi * 32);
        uint32_t w = 0;
#pragma unroll
        for (int j = 0; j < 8; j++) {
            int4 v = p[j];
            w |= (uint32_t)(v.x != 0) << (j*4 + 0);
            w |= (uint32_t)(v.y != 0) << (j*4 + 1);
            w |= (uint32_t)(v.z != 0) << (j*4 + 2);
            w |= (uint32_t)(v.w != 0) << (j*4 + 3);
        }
        mb[wi] = w;
    } else if (bid < 13568) {
        int idx = (bid - 13312) * 256 + tid;
        int t = idx >> 5, pi = idx & 31;
        float theta = expf(-((2.0f * pi) / 64.0f) * logf(10000.0f));
        float ang = (float)t * theta;
        rt[idx] = make_float2(cosf(ang), sinf(ang));
    } else {
        int row = bid - 13568;
        const float4 f = ((const float4*)(x + (size_t)row * DD))[tid];
        int wid = tid >> 5, lane = tid & 31;

        float s = f.x + f.y + f.z + f.w;
#pragma unroll
        for (int o = 16; o; o >>= 1) s += __shfl_xor_sync(~0u, s, o);
        if (lane == 0) shm[wid] = s;
        __syncthreads();
        s = shm[lane & 7];
#pragma unroll
        for (int o = 4; o; o >>= 1) s += __shfl_xor_sync(~0u, s, o);
        float mean = s * (1.0f / DD);

        float dx = f.x - mean, dy = f.y - mean, dz = f.z - mean, dw = f.w - mean;
        float v = dx*dx + dy*dy + dz*dz + dw*dw;
#pragma unroll
        for (int o = 16; o; o >>= 1) v += __shfl_xor_sync(~0u, v, o);
        __syncthreads();
        if (lane == 0) shm[wid] = v;
        __syncthreads();
        v = shm[lane & 7];
#pragma unroll
        for (int o = 4; o; o >>= 1) v += __shfl_xor_sync(~0u, v, o);
        float inv = rsqrtf(v * (1.0f / DD) + 1e-5f);

        const float4 g4 = ((const float4*)g1)[tid];
        const float4 b4 = ((const float4*)b1v)[tid];
        uint2 st;
        st.x = packh2(dx*inv*g4.x + b4.x, dy*inv*g4.y + b4.y);
        st.y = packh2(dz*inv*g4.z + b4.z, dw*inv*g4.w + b4.w);
        *(uint2*)(h16out + (size_t)row * DD + tid*4) = st;
    }
}

// ================= LayerNorm -> fp16 (standalone for LN2) =================
__global__ void ln16_kernel(const float* __restrict__ x, const float* __restrict__ g,
                            const float* __restrict__ b, __half* __restrict__ out) {
    int row = blockIdx.x;
    int tid = threadIdx.x;
    const float4 f = ((const float4*)(x + (size_t)row * DD))[tid];
    __shared__ float sw[8];
    int wid = tid >> 5, lane = tid & 31;

    float s = f.x + f.y + f.z + f.w;
#pragma unroll
    for (int o = 16; o; o >>= 1) s += __shfl_xor_sync(~0u, s, o);
    if (lane == 0) sw[wid] = s;
    __syncthreads();
    s = sw[lane & 7];
#pragma unroll
    for (int o = 4; o; o >>= 1) s += __shfl_xor_sync(~0u, s, o);
    float mean = s * (1.0f / DD);

    float dx = f.x - mean, dy = f.y - mean, dz = f.z - mean, dw = f.w - mean;
    float v = dx*dx + dy*dy + dz*dz + dw*dw;
#pragma unroll
    for (int o = 16; o; o >>= 1) v += __shfl_xor_sync(~0u, v, o);
    __syncthreads();
    if (lane == 0) sw[wid] = v;
    __syncthreads();
    v = sw[lane & 7];
#pragma unroll
    for (int o = 4; o; o >>= 1) v += __shfl_xor_sync(~0u, v, o);
    float inv = rsqrtf(v * (1.0f / DD) + 1e-5f);

    const float4 g4 = ((const float4*)g)[tid];
    const float4 b4 = ((const float4*)b)[tid];
    uint2 st;
    st.x = packh2(dx*inv*g4.x + b4.x, dy*inv*g4.y + b4.y);
    st.y = packh2(dz*inv*g4.z + b4.z, dw*inv*g4.w + b4.w);
    *(uint2*)(out + (size_t)row * DD + tid*4) = st;
}

// ================= per-(b, key-block) all/any flags (reads packed mb) ==========
__global__ void maskflags_kernel(const uint32_t* __restrict__ mb, int* __restrict__ mf) {
    int bs = blockIdx.x;
    int b = bs >> 5, sblk = bs & 31;
    uint32_t av = 0xFFFFFFFFu, ov = 0u;
    for (int t = threadIdx.x; t < TT; t += 256) {
        const uint32_t* p = mb + ((size_t)(b*TT) + t)*(TT/32) + sblk*2;
        uint32_t w0 = p[0], w1 = p[1];
        av &= (w0 & w1); ov |= (w0 | w1);
    }
    __shared__ uint32_t sa[8], so[8];
#pragma unroll
    for (int o = 16; o; o >>= 1) {
        av &= __shfl_xor_sync(~0u, av, o);
        ov |= __shfl_xor_sync(~0u, ov, o);
    }
    int w = threadIdx.x >> 5;
    if ((threadIdx.x & 31) == 0) { sa[w] = av; so[w] = ov; }
    __syncthreads();
    if (threadIdx.x == 0) {
        av = 0xFFFFFFFFu; ov = 0u;
#pragma unroll
        for (int i = 0; i < 8; i++) { av &= sa[i]; ov |= so[i]; }
        mf[bs] = ((av == 0xFFFFFFFFu) ? 2 : 0) | (ov ? 1 : 0);
    }
}

// ================= mma.sync fp16 GEMM (128x128, 3-stage, 2 CTA/SM) — proven ====
// EPI bits: 1=ROPE(z<2), 2=BIAS, 4=RELU, 8=RES, 16=F16OUT, 32=QSCALE(z==0)
template<int EPI>
__global__ void __launch_bounds__(256, 2) mm16(
        const __half* __restrict__ A, const __half* __restrict__ B0,
        const float* __restrict__ bias, const float* __restrict__ res,
        float* __restrict__ outF, __half* __restrict__ outH0,
        int N, int K, long zsB, long zsC, const float2* __restrict__ rt) {
    extern __shared__ char smem_raw[];
    const uint32_t sbr = smem_u32(smem_raw);
    const uint32_t sb = (sbr + 1023) & ~1023u;

    const int tid = threadIdx.x, wid = tid >> 5, lane = tid & 31;
    const int wm = wid >> 1, wn = wid & 1;
    const int m0 = blockIdx.y << 7, n0 = blockIdx.x << 7;
    const int NC = K >> 6;

    const __half* Bw = B0 + (size_t)blockIdx.z * zsB;
    __half* outH = outH0 + (size_t)blockIdx.z * zsC;

    const __half* Ag = A  + (size_t)m0 * K;
    const __half* Bg = Bw + (size_t)n0 * K;

    const int rq_r = tid >> 3, rq_q = tid & 7;
    const __half* agp = Ag + (size_t)rq_r * K + (rq_q << 3);
    const __half* bgp = Bg + (size_t)rq_r * K + (rq_q << 3);
    uint32_t so = (uint32_t)((rq_r << 7) + (rq_q << 4));
    so ^= (so >> 3) & 0x70;
    const size_t rowstep = (size_t)32 * K;

    auto issue_load = [&](int c, int stg) {
        uint32_t sA = sb + stg * 32768;
#pragma unroll
        for (int v = 0; v < 4; v++) {
            CPA(sA + so + v*4096,         agp + (size_t)c*64 + v*rowstep);
            CPA(sA + 16384 + so + v*4096, bgp + (size_t)c*64 + v*rowstep);
        }
    };

    float acc[2][8][4];
#pragma unroll
    for (int mi = 0; mi < 2; mi++)
#pragma unroll
        for (int ni = 0; ni < 8; ni++)
#pragma unroll
            for (int v = 0; v < 4; v++) acc[mi][ni][v] = 0.f;

#pragma unroll
    for (int s = 0; s < 3; s++) { issue_load(s, s); CPCOMMIT; }

    for (int c = 0; c < NC; c++) {
        CPWAIT(2);
        __syncthreads();
        int stg = c % 3;
        uint32_t sA = sb + stg * 32768;
        uint32_t sB = sA + 16384;
#pragma unroll
        for (int kk = 0; kk < 4; kk++) {
            uint32_t a[2][4], b0[8], b1[8];
            const int kb = kk*32 + ((lane >> 4) << 4);
#pragma unroll
            for (int mi = 0; mi < 2; mi++) {
                int row = wm*32 + mi*16 + (lane & 15);
                uint32_t o = (uint32_t)(row*128 + kb); o ^= (o >> 3) & 0x70;
                ldsm4(a[mi][0], a[mi][1], a[mi][2], a[mi][3], sA + o);
            }
#pragma unroll
            for (int j = 0; j < 4; j++) {
                int row = wn*64 + j*16 + (lane & 15);
                uint32_t o = (uint32_t)(row*128 + kb); o ^= (o >> 3) & 0x70;
                ldsm4(b0[2*j], b0[2*j+1], b1[2*j], b1[2*j+1], sB + o);
            }
#pragma unroll
            for (int mi = 0; mi < 2; mi++)
#pragma unroll
                for (int ni = 0; ni < 8; ni++)
                    mma_f16(acc[mi][ni], a[mi], b0[ni], b1[ni]);
        }
        __syncthreads();
        if (c + 3 < NC) issue_load(c + 3, stg);
        CPCOMMIT;
    }
    CPWAIT(0);

    // epilogue
    const int g = lane >> 2, tq = lane & 3;
    const bool doRope = (EPI & 1) && (blockIdx.z < 2);
    const bool doQs   = (EPI & 32) && (blockIdx.z == 0);
#pragma unroll
    for (int mi = 0; mi < 2; mi++) {
#pragma unroll
        for (int ni = 0; ni < 8; ni++) {
            const int colb = n0 + wn*64 + ni*8 + 2*tq;
            float2 bv = make_float2(0.f, 0.f);
            if (EPI & 2) bv = *(const float2*)(bias + colb);
#pragma unroll
            for (int rh = 0; rh < 2; rh++) {
                int row = m0 + wm*32 + mi*16 + g + rh*8;
                float v0 = acc[mi][ni][rh*2], v1 = acc[mi][ni][rh*2+1];
                if (EPI & 2) { v0 += bv.x; v1 += bv.y; }
                if (EPI & 4) { v0 = fmaxf(v0, 0.f); v1 = fmaxf(v1, 0.f); }
                if (doRope) {
                    int t = row & (TT-1);
                    int pi = (colb & 63) >> 1;
                    float2 cs = rt[t*32 + pi];
                    float nv0 = v0*cs.x - v1*cs.y;
                    float nv1 = v0*cs.y + v1*cs.x;
                    v0 = nv0; v1 = nv1;
                }
                if (doQs) { v0 *= QSCALE_LOG2E; v1 *= QSCALE_LOG2E; }
                if (EPI & 8) {
                    float2 rv = *(const float2*)(res + (size_t)row*N + colb);
                    v0 += rv.x; v1 += rv.y;
                }
                if (EPI & 16) {
                    uint32_t hv = packh2(v0, v1);
                    *(uint32_t*)(outH + (size_t)row*N + colb) = hv;
                } else {
                    *(float2*)(outF + (size_t)row*N + colb) = make_float2(v0, v1);
                }
            }
        }
    }
}

// ================= flash attention: 64-row Q tiles, 128 threads, 4 CTA/SM =======
__global__ void __launch_bounds__(128, 4) flash_kernel(
        const __half* __restrict__ qg, const __half* __restrict__ kg, const __half* __restrict__ vg,
        const uint32_t* __restrict__ mb, const int* __restrict__ mf,
        __half* __restrict__ attH) {
    extern __shared__ char smem_raw[];
    const uint32_t sbr = smem_u32(smem_raw);
    const uint32_t sb = (sbr + 1023) & ~1023u;
    char* base = smem_raw + (int)(sb - sbr);

    // layout: Q 8K | K 2x8K | V 2x8K | P 8K  = 48K
    const uint32_t sQ = sb, sK = sb + 8192, sV = sb + 24576, sP = sb + 40960;

    int bh = blockIdx.y, b = bh >> 4, h = bh & 15;
    int t0 = blockIdx.x << 6;                 // 64-row Q tile
    int tid = threadIdx.x, wid = tid >> 5, lane = tid & 31;
    int g = lane >> 2, tq = lane & 3;

    int nse = 0;
    const int* mfp = mf + b*32;
#pragma unroll
    for (int i2 = 0; i2 < 32; i2++) if (mfp[i2] & 1) nse = i2 + 1;

    const __half* kbase = kg + ((size_t)(b*TT)) * DD + h*64;
    const __half* vbase = vg + ((size_t)(b*TT)) * DD + h*64;

    const int lr = tid >> 3, lq = tid & 7;    // lr 0..15, lq 0..7
    uint32_t lso = (uint32_t)((lr << 7) + (lq << 4));
    lso ^= (lso >> 3) & 0x70;

    auto issue_kv = [&](int s0, int stg) {
        const __half* ks = kbase + (size_t)s0 * DD;
        const __half* vs = vbase + (size_t)s0 * DD;
#pragma unroll
        for (int v = 0; v < 4; v++) {
            CPA(sK + stg*8192 + lso + v*2048, ks + (size_t)(lr + v*16)*DD + lq*8);
            CPA(sV + stg*8192 + lso + v*2048, vs + (size_t)(lr + v*16)*DD + lq*8);
        }
    };

    issue_kv(0, 0); CPCOMMIT;

    // load Q tile (64 rows x 128B, swizzled): 128 thr x 16B x 4 passes
    {
        const __half* src = qg + ((size_t)(b*TT) + t0) * DD + h*64;
#pragma unroll
        for (int v = 0; v < 4; v++) {
            int p = tid + (v << 7);
            int t = p >> 3, dq = p & 7;
            uint32_t o = (uint32_t)(t*128 + dq*16); o ^= (o >> 3) & 0x70;
            *(uint4*)(base + o) = *(const uint4*)(src + (size_t)t*DD + dq*8);
        }
    }

    float mrow[2] = {-1e30f, -1e30f};
    float lrow[2] = {0.f, 0.f};
    float o[8][4];
#pragma unroll
    for (int ni = 0; ni < 8; ni++)
#pragma unroll
        for (int v = 0; v < 4; v++) o[ni][v] = 0.f;

    for (int i = 0; i < nse; i++) {
        if (i + 1 < nse) { issue_kv((i+1)*64, (i+1) & 1); CPCOMMIT; CPWAIT(1); }
        else             { CPWAIT(0); }
        __syncthreads();
        const uint32_t kS = sK + (i & 1)*8192;
        const uint32_t vS = sV + (i & 1)*8192;
        const int s0 = i * 64;

        // S = Q K^T
        float sa[8][4];
#pragma unroll
        for (int ni = 0; ni < 8; ni++)
#pragma unroll
            for (int v = 0; v < 4; v++) sa[ni][v] = 0.f;
#pragma unroll
        for (int kk = 0; kk < 4; kk++) {
            const int kb = kk*32 + ((lane >> 4) << 4);
            uint32_t a[4], b0[8], b1[8];
            {
                int row = wid*16 + (lane & 15);
                uint32_t oo = (uint32_t)(row*128 + kb); oo ^= (oo >> 3) & 0x70;
                ldsm4(a[0], a[1], a[2], a[3], sQ + oo);
            }
#pragma unroll
            for (int j = 0; j < 4; j++) {
                int row = j*16 + (lane & 15);
                uint32_t oo = (uint32_t)(row*128 + kb); oo ^= (oo >> 3) & 0x70;
                ldsm4(b0[2*j], b0[2*j+1], b1[2*j], b1[2*j+1], kS + oo);
            }
#pragma unroll
            for (int ni = 0; ni < 8; ni++) mma_f16(sa[ni], a, b0[ni], b1[ni]);
        }

        if (!(mfp[i] & 2)) {
            int tr0 = t0 + wid*16 + g;
            const uint32_t* mrow0 = mb + ((size_t)(b*TT) + tr0)*(TT/32) + (s0 >> 5);
            const uint32_t* mrow1 = mrow0 + 8*(TT/32);
            uint32_t w00 = mrow0[0], w01 = mrow0[1];
            uint32_t w10 = mrow1[0], w11 = mrow1[1];
#pragma unroll
            for (int ni = 0; ni < 8; ni++) {
#pragma unroll
                for (int v = 0; v < 4; v++) {
                    int sc = ni*8 + 2*tq + (v & 1);
                    uint32_t wsel = (v < 2) ? ((sc < 32) ? w00 : w01)
                                            : ((sc < 32) ? w10 : w11);
                    bool ok = (wsel >> (sc & 31)) & 1u;
                    if (!ok) sa[ni][v] = -1e30f;
                }
            }
        }

        uint32_t pp[8][2];
#pragma unroll
        for (int rh = 0; rh < 2; rh++) {
            float mx = -1e30f;
#pragma unroll
            for (int ni = 0; ni < 8; ni++)
                mx = fmaxf(mx, fmaxf(sa[ni][rh*2], sa[ni][rh*2+1]));
            mx = fmaxf(mx, __shfl_xor_sync(0xffffffffu, mx, 1));
            mx = fmaxf(mx, __shfl_xor_sync(0xffffffffu, mx, 2));
            float mn = fmaxf(mrow[rh], mx);
            float alpha = exp2f(mrow[rh] - mn);
            mrow[rh] = mn;
            float rs = 0.f;
#pragma unroll
            for (int ni = 0; ni < 8; ni++) {
                uint32_t ph = packh2(sa[ni][rh*2] - mn, sa[ni][rh*2+1] - mn);
                __half2 pe = h2exp2(*(__half2*)&ph);
                pp[ni][rh] = *(uint32_t*)&pe;
                float2 pf = __half22float2(pe);
                rs += pf.x + pf.y;
            }
            rs += __shfl_xor_sync(0xffffffffu, rs, 1);
            rs += __shfl_xor_sync(0xffffffffu, rs, 2);
            lrow[rh] = lrow[rh]*alpha + rs;
#pragma unroll
            for (int ni = 0; ni < 8; ni++) { o[ni][rh*2] *= alpha; o[ni][rh*2+1] *= alpha; }
        }

#pragma unroll
        for (int ni = 0; ni < 8; ni++) {
#pragma unroll
            for (int rh = 0; rh < 2; rh++) {
                int trow = wid*16 + g + rh*8;
                int scol = ni*8 + 2*tq;
                uint32_t oo = (uint32_t)(trow*128 + scol*2); oo ^= (oo >> 3) & 0x70;
                *(uint32_t*)(base + (sP - sb) + oo) = pp[ni][rh];
            }
        }
        __syncwarp();

        // O += P V
#pragma unroll
        for (int kk = 0; kk < 4; kk++) {
            uint32_t a[4], b0[8], b1[8];
            {
                int row = wid*16 + (lane & 15);
                uint32_t oo = (uint32_t)(row*128 + kk*32 + ((lane >> 4) << 4));
                oo ^= (oo >> 3) & 0x70;
                ldsm4(a[0], a[1], a[2], a[3], sP + oo);
            }
#pragma unroll
            for (int j = 0; j < 4; j++) {
                int rs_ = kk*16 + (lane & 15);
                uint32_t oo = (uint32_t)(rs_*128 + j*32 + ((lane >> 4) << 4));
                oo ^= (oo >> 3) & 0x70;
                ldsm4t(b0[2*j], b1[2*j], b0[2*j+1], b1[2*j+1], vS + oo);
            }
#pragma unroll
            for (int ni = 0; ni < 8; ni++) mma_f16(o[ni], a, b0[ni], b1[ni]);
        }
        __syncthreads();
    }

#pragma unroll
    for (int rh = 0; rh < 2; rh++) {
        float inv = 1.0f / lrow[rh];
        int t = t0 + wid*16 + g + rh*8;
        size_t rb = ((size_t)(b*TT) + t) * DD;
#pragma unroll
        for (int ni = 0; ni < 8; ni++) {
            int col = h*64 + ni*8 + 2*tq;
            uint32_t hv = packh2(o[ni][rh*2] * inv, o[ni][rh*2+1] * inv);
            *(uint32_t*)(attH + rb + col) = hv;
        }
    }
}

// ================= launch =================
template<typename T>
static T* symaddr(const void* sym) {
    void* p = nullptr;
    cudaGetSymbolAddress(&p, sym);
    return (T*)p;
}

extern "C" void kernel_launch(void* const* d_in, const int* in_sizes, int n_in,
                              void* d_out, int out_size) {
    const float* x      = (const float*)d_in[0];
    const int*   mask   = (const int*)  d_in[1];
    const float* wq     = (const float*)d_in[2];
    const float* wk     = (const float*)d_in[3];
    const float* wv     = (const float*)d_in[4];
    const float* w_proj = (const float*)d_in[5];
    const float* b_proj = (const float*)d_in[6];
    const float* ln1_g  = (const float*)d_in[7];
    const float* ln1_b  = (const float*)d_in[8];
    const float* ln2_g  = (const float*)d_in[9];
    const float* ln2_b  = (const float*)d_in[10];
    const float* w1     = (const float*)d_in[11];
    const float* b1     = (const float*)d_in[12];
    const float* w2     = (const float*)d_in[13];
    const float* b2     = (const float*)d_in[14];
    float* out = (float*)d_out;

    __half* h16   = symaddr<__half>(g_h16);
    __half* qkv   = symaddr<__half>(g_qkv);
    __half* att   = symaddr<__half>(g_att);
    float*  x2_   = symaddr<float>(g_x2);
    __half* h216  = symaddr<__half>(g_h216);
    __half* ff    = symaddr<__half>(g_ff);
    __half* wqkvT = symaddr<__half>(g_wqkvT);
    __half* wpT   = symaddr<__half>(g_wpT);
    __half* w1T   = symaddr<__half>(g_w1T);
    __half* w2T   = symaddr<__half>(g_w2T);
    uint32_t* mb  = symaddr<uint32_t>(g_mb);
    int*    mf    = symaddr<int>(g_mf);
    float2* rt    = symaddr<float2>(g_rt);

    const int SMEM_MM = 3*32768 + 1024;   // 99328
    const int SMEM_FL = 49152 + 1024;     // 50176 (4 CTA/SM: 196KB < 228KB)
    cudaFuncSetAttribute(mm16<49>, cudaFuncAttributeMaxDynamicSharedMemorySize, SMEM_MM);
    cudaFuncSetAttribute(mm16<10>, cudaFuncAttributeMaxDynamicSharedMemorySize, SMEM_MM);
    cudaFuncSetAttribute(mm16<22>, cudaFuncAttributeMaxDynamicSharedMemorySize, SMEM_MM);
    cudaFuncSetAttribute(flash_kernel, cudaFuncAttributeMaxDynamicSharedMemorySize, SMEM_FL);

    // fused preprocessing: wtall + packmask + ropetab + LN1
    prep_kernel<<<17664, 256>>>(wq, wk, wv, w_proj, w1, w2,
                                wqkvT, wpT, w1T, w2T,
                                mask, mb, rt, x, ln1_g, ln1_b, h16);
    maskflags_kernel<<<BB*32, 256>>>(mb, mf);

    // fused QKV GEMM: RoPE (z<2) + q-scale incl. log2e (z==0), fp16 out
    mm16<49><<<dim3(DD/128, NROWS/128, 3), 256, SMEM_MM>>>(
        h16, wqkvT, nullptr, nullptr, nullptr, qkv, DD, DD,
        (long)DD*DD, (long)NROWS*DD, rt);

    // flash attention (exp2 domain, 64-row tiles, 4 CTA/SM)
    flash_kernel<<<dim3(TT/64, NBH), 128, SMEM_FL>>>(
        qkv, qkv + (size_t)NROWS*DD, qkv + 2*(size_t)NROWS*DD, mb, mf, att);

    // proj + bias + residual -> x2 (fp32)
    mm16<10><<<dim3(DD/128, NROWS/128), 256, SMEM_MM>>>(
        att, wpT, b_proj, x, x2_, nullptr, DD, DD, 0L, 0L, rt);

    // LN2 -> fp16
    ln16_kernel<<<NROWS, 256>>>(x2_, ln2_g, ln2_b, h216);

    // MLP1: bias + relu -> fp16
    mm16<22><<<dim3(FF/128, NROWS/128), 256, SMEM_MM>>>(
        h216, w1T, b1, nullptr, nullptr, ff, FF, DD, 0L, 0L, rt);

    // MLP2: bias + residual -> out (fp32)
    mm16<10><<<dim3(DD/128, NROWS/128), 256, SMEM_MM>>>(
        ff, w2T, b2, x2_, out, nullptr, DD, FF, 0L, 0L, rt);
}